// round 4
// baseline (speedup 1.0000x reference)
#include <cuda_runtime.h>
#include <cstdint>

// Problem constants (fixed by the dataset).
#define N_NODES   50000
#define REL_NUM   16
#define D_IN      64
#define D_OUT     64

// 204.8 MB scratch for per-(node, relation) transformed features.
// Layout: g_transformed[((n * REL_NUM) + r) * D_OUT + o]
__device__ float g_transformed[(size_t)N_NODES * REL_NUM * D_OUT];

// ---------------------------------------------------------------------------
// Phase 1: T[n, r, :] = h[n, :] @ W[r]   (fp32 SGEMM-style tile)
// Block: 256 threads, tile = 64 nodes x 64 out-cols, one relation per block.y.
// Each thread computes a 4x4 micro-tile. h tile stored transposed in smem so
// both operands of the inner loop are float4 LDS with broadcast/contiguous
// access (a: 2 distinct 16B addrs per warp -> broadcast; b: 256B contiguous).
// ---------------------------------------------------------------------------
__global__ __launch_bounds__(256, 2)
void transform_kernel(const float* __restrict__ h,
                      const float* __restrict__ W,
                      int n_nodes)
{
    __shared__ float hsT[D_IN][64];   // [d][node_local]
    __shared__ float Ws[D_IN][D_OUT]; // [d][o]  (same layout as W[rel])

    const int rel = blockIdx.y;
    const int n0  = blockIdx.x * 64;
    const int tid = threadIdx.x;

    // Load W[rel] (16 KB) straight into smem (layout identical).
    {
        const float4* Wg  = reinterpret_cast<const float4*>(W + (size_t)rel * D_IN * D_OUT);
        float4*       Wsv = reinterpret_cast<float4*>(&Ws[0][0]);
        #pragma unroll
        for (int i = tid; i < (D_IN * D_OUT) / 4; i += 256)
            Wsv[i] = Wg[i];
    }

    // Load the 64-node h tile, transposing into hsT[d][n]. Out-of-range nodes -> 0.
    #pragma unroll
    for (int i = tid; i < (64 * D_IN) / 4; i += 256) {
        const int n  = i / (D_IN / 4);       // 0..63
        const int c4 = (i % (D_IN / 4)) * 4; // d base
        float4 v;
        if (n0 + n < n_nodes)
            v = *reinterpret_cast<const float4*>(h + (size_t)(n0 + n) * D_IN + c4);
        else
            v = make_float4(0.f, 0.f, 0.f, 0.f);
        hsT[c4 + 0][n] = v.x;
        hsT[c4 + 1][n] = v.y;
        hsT[c4 + 2][n] = v.z;
        hsT[c4 + 3][n] = v.w;
    }
    __syncthreads();

    const int cg = tid & 15;   // col group: cols [cg*4, cg*4+4)
    const int ng = tid >> 4;   // node group: nodes [ng*4, ng*4+4)

    float acc[4][4] = {};

    #pragma unroll 16
    for (int d = 0; d < D_IN; d++) {
        const float4 a = *reinterpret_cast<const float4*>(&hsT[d][ng * 4]);
        const float4 b = *reinterpret_cast<const float4*>(&Ws[d][cg * 4]);

        acc[0][0] = fmaf(a.x, b.x, acc[0][0]);
        acc[0][1] = fmaf(a.x, b.y, acc[0][1]);
        acc[0][2] = fmaf(a.x, b.z, acc[0][2]);
        acc[0][3] = fmaf(a.x, b.w, acc[0][3]);
        acc[1][0] = fmaf(a.y, b.x, acc[1][0]);
        acc[1][1] = fmaf(a.y, b.y, acc[1][1]);
        acc[1][2] = fmaf(a.y, b.z, acc[1][2]);
        acc[1][3] = fmaf(a.y, b.w, acc[1][3]);
        acc[2][0] = fmaf(a.z, b.x, acc[2][0]);
        acc[2][1] = fmaf(a.z, b.y, acc[2][1]);
        acc[2][2] = fmaf(a.z, b.z, acc[2][2]);
        acc[2][3] = fmaf(a.z, b.w, acc[2][3]);
        acc[3][0] = fmaf(a.w, b.x, acc[3][0]);
        acc[3][1] = fmaf(a.w, b.y, acc[3][1]);
        acc[3][2] = fmaf(a.w, b.z, acc[3][2]);
        acc[3][3] = fmaf(a.w, b.w, acc[3][3]);
    }

    // Write the 4x4 micro-tile: T[n, rel, cg*4 .. cg*4+3]
    #pragma unroll
    for (int i = 0; i < 4; i++) {
        const int n = n0 + ng * 4 + i;
        if (n < n_nodes) {
            float4 w = make_float4(acc[i][0], acc[i][1], acc[i][2], acc[i][3]);
            *reinterpret_cast<float4*>(
                &g_transformed[((size_t)n * REL_NUM + rel) * D_OUT + cg * 4]) = w;
        }
    }
}

// ---------------------------------------------------------------------------
// Phase 2: per edge e, out[dst_e] += T[src_e, rel_e, :] * norm_e.
// 16 threads cooperate on one edge (float4 each). Vector reductions
// (red.global.add.v4.f32, sm_90+) quarter the atomic-op count; the output
// region is 12.8 MB -> fully L2-resident, so atomics never touch DRAM.
// ---------------------------------------------------------------------------
__global__ __launch_bounds__(256)
void scatter_kernel(const float* __restrict__ norm,
                    const int*   __restrict__ src,
                    const int*   __restrict__ dst,
                    const int*   __restrict__ rel,
                    float*       __restrict__ out,
                    long long    n_edges)
{
    const long long idx = (long long)blockIdx.x * blockDim.x + threadIdx.x;
    const long long e   = idx >> 4;
    if (e >= n_edges) return;
    const int sub = (int)(idx & 15);

    const int   s  = src[e];
    const int   t  = dst[e];
    const int   r  = rel[e];
    const float nm = norm[e];

    const float4 v = *reinterpret_cast<const float4*>(
        &g_transformed[((size_t)s * REL_NUM + r) * D_OUT + sub * 4]);

    const float mx = v.x * nm;
    const float my = v.y * nm;
    const float mz = v.z * nm;
    const float mw = v.w * nm;

    float* p = out + (size_t)t * D_OUT + sub * 4;
    asm volatile("red.global.add.v4.f32 [%0], {%1, %2, %3, %4};"
                 :: "l"(p), "f"(mx), "f"(my), "f"(mz), "f"(mw)
                 : "memory");
}

// ---------------------------------------------------------------------------
// Phase 3: in-place ReLU on the accumulated output.
// ---------------------------------------------------------------------------
__global__ __launch_bounds__(256)
void relu_kernel(float* __restrict__ out, int n4)
{
    const int i = blockIdx.x * blockDim.x + threadIdx.x;
    if (i >= n4) return;
    float4 v = reinterpret_cast<float4*>(out)[i];
    v.x = fmaxf(v.x, 0.f);
    v.y = fmaxf(v.y, 0.f);
    v.z = fmaxf(v.z, 0.f);
    v.w = fmaxf(v.w, 0.f);
    reinterpret_cast<float4*>(out)[i] = v;
}

extern "C" void kernel_launch(void* const* d_in, const int* in_sizes, int n_in,
                              void* d_out, int out_size)
{
    // metadata order: h, weight, norm, src, dst, rel_type
    const float* h    = (const float*)d_in[0];
    const float* W    = (const float*)d_in[1];
    const float* norm = (const float*)d_in[2];
    const int*   src  = (const int*)d_in[3];
    const int*   dst  = (const int*)d_in[4];
    const int*   rel  = (const int*)d_in[5];
    float*       out  = (float*)d_out;

    const int       n_nodes = in_sizes[0] / D_IN;   // 50000
    const long long n_edges = in_sizes[3];          // 1,600,000

    // d_out is poisoned; it doubles as the atomic accumulator, so zero it.
    cudaMemsetAsync(d_out, 0, (size_t)out_size * sizeof(float), 0);

    // Phase 1: per-(node, relation) transform.
    {
        dim3 grid((n_nodes + 63) / 64, REL_NUM);
        transform_kernel<<<grid, 256>>>(h, W, n_nodes);
    }

    // Phase 2: edge gather + scaled vector-atomic scatter.
    {
        const long long threads = n_edges * 16;
        const int blocks = (int)((threads + 255) / 256);
        scatter_kernel<<<blocks, 256>>>(norm, src, dst, rel, out, n_edges);
    }

    // Phase 3: ReLU.
    {
        const int n4 = out_size / 4;
        relu_kernel<<<(n4 + 255) / 256, 256>>>(out, n4);
    }
}

// round 5
// speedup vs baseline: 1.3035x; 1.3035x over previous
#include <cuda_runtime.h>
#include <cuda_fp16.h>
#include <cstdint>

#define N_NODES   50000
#define REL_NUM   16
#define D_IN      64
#define D_OUT     64

// 102.4 MB fp16 scratch: T[n][r][o], row (n,r) = 64 halfs = 128 B.
__device__ __half g_transformed[(size_t)N_NODES * REL_NUM * D_OUT];

// ---- packed-fp32 helpers -------------------------------------------------
__device__ __forceinline__ unsigned long long splat2(float x) {
    unsigned long long r;
    asm("mov.b64 %0, {%1, %1};" : "=l"(r) : "f"(x));
    return r;
}
__device__ __forceinline__ unsigned long long fma2(unsigned long long a,
                                                   unsigned long long b,
                                                   unsigned long long c) {
    unsigned long long d;
    asm("fma.rn.f32x2 %0, %1, %2, %3;" : "=l"(d) : "l"(a), "l"(b), "l"(c));
    return d;
}
// f32x2 (lo=even col, hi=odd col) -> half2 bits (lo half first)
__device__ __forceinline__ unsigned cvt_f32x2_h2(unsigned long long p) {
    float lo, hi;
    asm("mov.b64 {%0, %1}, %2;" : "=f"(lo), "=f"(hi) : "l"(p));
    unsigned r;
    asm("cvt.rn.f16x2.f32 %0, %1, %2;" : "=r"(r) : "f"(hi), "f"(lo));
    return r;
}

// ---------------------------------------------------------------------------
// Phase 1: T[n, rel, :] = fp16( h[n, :] @ W[rel] )
// 128 threads, tile 128 nodes x 64 cols, 8x8 micro-tile per thread.
// FFMA2 packed math; h transposed into smem via 4x4 register transpose
// (conflict-free float4 writes); W stored chunk-permuted so the 8 col-groups'
// LDS.128 land in 8 distinct bank groups.
// ---------------------------------------------------------------------------
__global__ __launch_bounds__(128)
void transform_kernel(const float* __restrict__ h,
                      const float* __restrict__ W,
                      int n_nodes)
{
    __shared__ float hsT[D_IN * 128];   // [d][n] , row = 128 floats = 32 chunks
    __shared__ float Ws [D_IN * D_OUT]; // [d][chunk-permuted cols]

    const int rel = blockIdx.y;
    const int n0  = blockIdx.x * 128;
    const int tid = threadIdx.x;

    // --- Load W[rel] with chunk permutation p(c) = (c>>1) | ((c&1)<<3) ---
    {
        const float4* Wg  = reinterpret_cast<const float4*>(W + (size_t)rel * D_IN * D_OUT);
        float4*       Ws4 = reinterpret_cast<float4*>(Ws);
        #pragma unroll
        for (int i = tid; i < (D_IN * D_OUT) / 4; i += 128) {
            const int d = i >> 4;
            const int c = i & 15;
            const int p = (c >> 1) | ((c & 1) << 3);
            Ws4[d * 16 + p] = Wg[i];
        }
    }

    // --- Load h tile with 4x4 register transpose -> hsT[d][n] ---
    {
        float4* hsT4 = reinterpret_cast<float4*>(hsT);
        const int nb    = tid & 31;   // node quad: nodes nb*4 .. nb*4+3
        const int dquad = tid >> 2;   // unused marker
        (void)dquad;
        const int dq = tid >> 5;      // 0..3
        #pragma unroll
        for (int kk = 0; kk < 4; kk++) {
            const int d4 = (dq + kk * 4) * 4;   // dims d4 .. d4+3
            float hv[4][4];
            #pragma unroll
            for (int k = 0; k < 4; k++) {
                const int n = n0 + nb * 4 + k;
                float4 v;
                if (n < n_nodes)
                    v = *reinterpret_cast<const float4*>(h + (size_t)n * D_IN + d4);
                else
                    v = make_float4(0.f, 0.f, 0.f, 0.f);
                hv[k][0] = v.x; hv[k][1] = v.y; hv[k][2] = v.z; hv[k][3] = v.w;
            }
            #pragma unroll
            for (int j = 0; j < 4; j++) {
                float4 w = make_float4(hv[0][j], hv[1][j], hv[2][j], hv[3][j]);
                hsT4[(d4 + j) * 32 + nb] = w;
            }
        }
    }
    __syncthreads();

    const int cg = tid & 7;    // cols cg*8 .. cg*8+7
    const int ng = tid >> 3;   // nodes ng*8 .. ng*8+7

    // acc[i][j2]: f32x2 over col pair (cg*8+2*j2, +1) for node ng*8+i.
    unsigned long long acc[8][4];
    #pragma unroll
    for (int i = 0; i < 8; i++)
        #pragma unroll
        for (int j = 0; j < 4; j++) acc[i][j] = 0ull;

    const float4*     hsT4 = reinterpret_cast<const float4*>(hsT);
    const ulonglong2* Wsu  = reinterpret_cast<const ulonglong2*>(Ws); // [64][16] chunks

    #pragma unroll 8
    for (int d = 0; d < D_IN; d++) {
        const float4 a0 = hsT4[d * 32 + ng * 2];
        const float4 a1 = hsT4[d * 32 + ng * 2 + 1];
        // logical chunks 2*cg and 2*cg+1 live at permuted positions cg, cg+8
        const ulonglong2 b0 = Wsu[d * 16 + cg];       // cols 8cg+0..3 (2 pairs)
        const ulonglong2 b1 = Wsu[d * 16 + cg + 8];   // cols 8cg+4..7

        float a[8] = {a0.x, a0.y, a0.z, a0.w, a1.x, a1.y, a1.z, a1.w};
        #pragma unroll
        for (int i = 0; i < 8; i++) {
            const unsigned long long aa = splat2(a[i]);
            acc[i][0] = fma2(aa, b0.x, acc[i][0]);
            acc[i][1] = fma2(aa, b0.y, acc[i][1]);
            acc[i][2] = fma2(aa, b1.x, acc[i][2]);
            acc[i][3] = fma2(aa, b1.y, acc[i][3]);
        }
    }

    // Epilogue: fp16 rows, 16 B per node row segment.
    #pragma unroll
    for (int i = 0; i < 8; i++) {
        const int n = n0 + ng * 8 + i;
        if (n < n_nodes) {
            uint4 o;
            o.x = cvt_f32x2_h2(acc[i][0]);
            o.y = cvt_f32x2_h2(acc[i][1]);
            o.z = cvt_f32x2_h2(acc[i][2]);
            o.w = cvt_f32x2_h2(acc[i][3]);
            __half* p = g_transformed + ((size_t)n * REL_NUM + rel) * D_OUT + cg * 8;
            *reinterpret_cast<uint4*>(p) = o;
        }
    }
}

// ---------------------------------------------------------------------------
// Phase 2: out[dst_e] += fp32(T[src_e, rel_e, :]) * norm_e.
// 8 threads/edge, 16 B fp16 gather each (row = 128 B, mostly L2-resident),
// two red.global.add.v4.f32 per thread into the L2-resident output.
// ---------------------------------------------------------------------------
__global__ __launch_bounds__(256)
void scatter_kernel(const float* __restrict__ norm,
                    const int*   __restrict__ src,
                    const int*   __restrict__ dst,
                    const int*   __restrict__ rel,
                    float*       __restrict__ out,
                    long long    n_edges)
{
    const long long idx = (long long)blockIdx.x * blockDim.x + threadIdx.x;
    const long long e   = idx >> 3;
    if (e >= n_edges) return;
    const int sub = (int)(idx & 7);

    const int   s  = src[e];
    const int   t  = dst[e];
    const int   r  = rel[e];
    const float nm = norm[e];

    const __half* row = g_transformed + ((size_t)s * REL_NUM + r) * D_OUT + sub * 8;
    const uint4 v = *reinterpret_cast<const uint4*>(row);

    float2 f0 = __half22float2(*reinterpret_cast<const __half2*>(&v.x));
    float2 f1 = __half22float2(*reinterpret_cast<const __half2*>(&v.y));
    float2 f2 = __half22float2(*reinterpret_cast<const __half2*>(&v.z));
    float2 f3 = __half22float2(*reinterpret_cast<const __half2*>(&v.w));

    float* p = out + (size_t)t * D_OUT + sub * 8;
    asm volatile("red.global.add.v4.f32 [%0], {%1, %2, %3, %4};"
                 :: "l"(p), "f"(f0.x * nm), "f"(f0.y * nm),
                    "f"(f1.x * nm), "f"(f1.y * nm) : "memory");
    asm volatile("red.global.add.v4.f32 [%0], {%1, %2, %3, %4};"
                 :: "l"(p + 4), "f"(f2.x * nm), "f"(f2.y * nm),
                    "f"(f3.x * nm), "f"(f3.y * nm) : "memory");
}

// ---------------------------------------------------------------------------
// Phase 3: in-place ReLU.
// ---------------------------------------------------------------------------
__global__ __launch_bounds__(256)
void relu_kernel(float* __restrict__ out, int n4)
{
    const int i = blockIdx.x * blockDim.x + threadIdx.x;
    if (i >= n4) return;
    float4 v = reinterpret_cast<float4*>(out)[i];
    v.x = fmaxf(v.x, 0.f);
    v.y = fmaxf(v.y, 0.f);
    v.z = fmaxf(v.z, 0.f);
    v.w = fmaxf(v.w, 0.f);
    reinterpret_cast<float4*>(out)[i] = v;
}

extern "C" void kernel_launch(void* const* d_in, const int* in_sizes, int n_in,
                              void* d_out, int out_size)
{
    // metadata order: h, weight, norm, src, dst, rel_type
    const float* h    = (const float*)d_in[0];
    const float* W    = (const float*)d_in[1];
    const float* norm = (const float*)d_in[2];
    const int*   src  = (const int*)d_in[3];
    const int*   dst  = (const int*)d_in[4];
    const int*   rel  = (const int*)d_in[5];
    float*       out  = (float*)d_out;

    const int       n_nodes = in_sizes[0] / D_IN;   // 50000
    const long long n_edges = in_sizes[3];          // 1,600,000

    cudaMemsetAsync(d_out, 0, (size_t)out_size * sizeof(float), 0);

    {
        dim3 grid((n_nodes + 127) / 128, REL_NUM);
        transform_kernel<<<grid, 128>>>(h, W, n_nodes);
    }
    {
        const long long threads = n_edges * 8;
        const int blocks = (int)((threads + 255) / 256);
        scatter_kernel<<<blocks, 256>>>(norm, src, dst, rel, out, n_edges);
    }
    {
        const int n4 = out_size / 4;
        relu_kernel<<<(n4 + 255) / 256, 256>>>(out, n4);
    }
}